// round 7
// baseline (speedup 1.0000x reference)
#include <cuda_runtime.h>
#include <cuda_fp16.h>
#include <cstdint>
#include <cfloat>

#define NPTS 1536
#define TLEN 20
#define HDIM 64
#define EDIM 16
#define MDIM 128
#define IPB  4              // i's per block (one per warp)
#define JC   32             // j rows per chunk
#define NCHUNK 48
#define JSPLIT 8            // j-range splits
#define CPB (NCHUNK / JSPLIT)   // 6
#define THREADS 128
#define APITCH 144          // halves per smem row (72 words == 8 mod 32: LDS.64 conflict-free)

// scratch (__device__ globals: allocation-free rule). Stored k-PERMUTED (see mperm).
__device__ __half g_Ah[NPTS * MDIM];
__device__ __half g_Bh[NPTS * MDIM];
__device__ __half g_W2h[HDIM * MDIM];   // W2^T, h-major, permuted fp16

// Permutation within each 16-k group so mma fragment halves are contiguous:
// logical order per group: [0,1,8,9, 2,3,10,11, 4,5,12,13, 6,7,14,15]
__host__ __device__ __forceinline__ int mperm(int m) {
    int g = m >> 4, w = m & 15;
    int pos = (w < 8) ? ((w >> 1) * 4 + (w & 1))
                      : (((w - 8) >> 1) * 4 + 2 + (w & 1));
    return g * 16 + pos;
}

// ---------------------------------------------------------------------------
// Precompute: A[j,m], B[j,m] (fp16, permuted) + W2^T fp16 permuted + zero out
// grid = NPTS, 128 threads (one per m)
// ---------------------------------------------------------------------------
__global__ void prep_kernel(const float* __restrict__ hidden,
                            const float* __restrict__ gt,
                            const float* __restrict__ We,
                            const float* __restrict__ be,
                            const float* __restrict__ W1,
                            const float* __restrict__ b1,
                            const float* __restrict__ W2,
                            float* __restrict__ out) {
    int j = blockIdx.x;
    int m = threadIdx.x;               // 0..127
    __shared__ float hs[HDIM];
    __shared__ float ev[2];
    if (m < HDIM) hs[m] = hidden[j * HDIM + m];
    if (m < 2)    ev[m] = gt[(j * TLEN + (TLEN - 1)) * 2 + m];
    __syncthreads();

    float p0 = 0.f, p1 = 0.f, q = 0.f;
#pragma unroll
    for (int e = 0; e < EDIM; e++) {
        float wv = W1[(HDIM + e) * MDIM + m];
        p0 += We[e] * wv;
        p1 += We[EDIM + e] * wv;
        q  += be[e] * wv;
    }
    float s = 0.f;
#pragma unroll 8
    for (int h = 0; h < HDIM; h++) s += hs[h] * W1[h * MDIM + m];

    float d = ev[0] * p0 + ev[1] * p1;
    int mp = mperm(m);
    g_Bh[j * MDIM + mp] = __float2half(d);
    g_Ah[j * MDIM + mp] = __float2half(s + d + q + b1[m]);

    if (m < HDIM) out[j * HDIM + m] = 0.f;                 // zero output (atomicMax base)
    if (j < HDIM) g_W2h[j * MDIM + mp] = __float2half(W2[m * HDIM + j]);
}

// ---------------------------------------------------------------------------
// Main: grid = (NPTS/IPB)*JSPLIT = 3072 blocks, 128 threads (4 warps).
// warp w -> i = ig*4 + w, all 64 h. Fragment-direct z, jt-outer (32-reg acc).
// ---------------------------------------------------------------------------
__global__ void __launch_bounds__(THREADS, 5)
main_kernel(const float* __restrict__ b2, float* __restrict__ out) {
    __shared__ __align__(16) __half A_s[2][JC * APITCH];   // 18432 B
    __shared__ __align__(16) __half w2t[HDIM * APITCH];    // 18432 B

    const int tid  = threadIdx.x;
    const int w    = tid >> 5;
    const int lane = tid & 31;
    const int ig   = blockIdx.x / JSPLIT;
    const int js   = blockIdx.x % JSPLIT;
    const int i    = ig * IPB + w;
    const int jc0  = js * CPB;

    const int fr = lane >> 2;          // fragment row (0..7)
    const int fc = lane & 3;           // fragment k-quad (0..3)

    // ---- stage W2^T via cp.async: 64 rows x 256B = 1024 16B-segs -> 8 iters ----
#pragma unroll
    for (int k = 0; k < 8; k++) {
        int idx = tid + k * THREADS;                       // 0..1023
        int h = idx >> 4, s = idx & 15;
        uint32_t dst = (uint32_t)__cvta_generic_to_shared(&w2t[h * APITCH + s * 8]);
        asm volatile("cp.async.ca.shared.global [%0], [%1], 16;"
                     :: "r"(dst), "l"(g_W2h + h * MDIM + s * 8) : "memory");
    }

    // ---- cp.async A-chunk staging: 32 rows x 256B = 512 segs -> 4 iters ----
    auto stageA = [&](int buf, int jc) {
        const __half* src = g_Ah + jc * JC * MDIM;
#pragma unroll
        for (int k = 0; k < 4; k++) {
            int idx = tid + k * THREADS;                   // 0..511 (16B segs)
            int row = idx >> 4, seg = idx & 15;
            uint32_t dst = (uint32_t)__cvta_generic_to_shared(
                &A_s[buf][row * APITCH + seg * 8]);
            asm volatile("cp.async.ca.shared.global [%0], [%1], 16;"
                         :: "r"(dst), "l"(src + idx * 8) : "memory");
        }
        asm volatile("cp.async.commit_group;" ::: "memory");
    };
    stageA(0, jc0);                    // commits W2 + first A together

    // ---- B[i] fragments (permuted: 4 contiguous halves per ks) ----
    __half2 bf[8][2];
#pragma unroll
    for (int ks = 0; ks < 8; ks++) {
        uint2 bv = *(const uint2*)&g_Bh[i * MDIM + ks * 16 + fc * 4];
        bf[ks][0] = *(__half2*)&bv.x;
        bf[ks][1] = *(__half2*)&bv.y;
    }

    float mx[8][2];
#pragma unroll
    for (int t = 0; t < 8; t++) { mx[t][0] = -FLT_MAX; mx[t][1] = -FLT_MAX; }

    const __half2 zero2 = __float2half2_rn(0.f);

    for (int c = 0; c < CPB; c++) {
        asm volatile("cp.async.wait_group 0;" ::: "memory");
        __syncthreads();
        if (c + 1 < CPB) stageA((c + 1) & 1, jc0 + c + 1);

        const __half* As = A_s[c & 1];

#pragma unroll
        for (int jt = 0; jt < 2; jt++) {
            float acc[8][4];
#pragma unroll
            for (int ht = 0; ht < 8; ht++)
#pragma unroll
                for (int r = 0; r < 4; r++) acc[ht][r] = 0.f;

#pragma unroll
            for (int ks = 0; ks < 8; ks++) {
                const int koff = ks * 16 + fc * 4;
                uint2 v0 = *(const uint2*)&As[(jt * 16 + fr) * APITCH + koff];     // a0|a2
                uint2 v1 = *(const uint2*)&As[(jt * 16 + 8 + fr) * APITCH + koff]; // a1|a3
                __half2 a0 = __hmax2(__hsub2(*(__half2*)&v0.x, bf[ks][0]), zero2);
                __half2 a2 = __hmax2(__hsub2(*(__half2*)&v0.y, bf[ks][1]), zero2);
                __half2 a1 = __hmax2(__hsub2(*(__half2*)&v1.x, bf[ks][0]), zero2);
                __half2 a3 = __hmax2(__hsub2(*(__half2*)&v1.y, bf[ks][1]), zero2);
                uint32_t za0 = *(uint32_t*)&a0, za1 = *(uint32_t*)&a1;
                uint32_t za2 = *(uint32_t*)&a2, za3 = *(uint32_t*)&a3;
#pragma unroll
                for (int ht = 0; ht < 8; ht++) {
                    uint2 wb = *(const uint2*)&w2t[(ht * 8 + fr) * APITCH + koff]; // b0|b1
                    asm volatile(
                        "mma.sync.aligned.m16n8k16.row.col.f32.f16.f16.f32 "
                        "{%0,%1,%2,%3},{%4,%5,%6,%7},{%8,%9},{%0,%1,%2,%3};"
                        : "+f"(acc[ht][0]), "+f"(acc[ht][1]),
                          "+f"(acc[ht][2]), "+f"(acc[ht][3])
                        : "r"(za0), "r"(za1), "r"(za2), "r"(za3),
                          "r"(wb.x), "r"(wb.y));
                }
            }
            // fold this j-tile into running max
#pragma unroll
            for (int ht = 0; ht < 8; ht++) {
                mx[ht][0] = fmaxf(mx[ht][0], fmaxf(acc[ht][0], acc[ht][2]));
                mx[ht][1] = fmaxf(mx[ht][1], fmaxf(acc[ht][1], acc[ht][3]));
            }
        }
    }

    // ---- reduce max across j-row lanes (same h: lane%4 groups) ----
#pragma unroll
    for (int ht = 0; ht < 8; ht++) {
#pragma unroll
        for (int s = 4; s < 32; s <<= 1) {
            mx[ht][0] = fmaxf(mx[ht][0], __shfl_xor_sync(0xffffffffu, mx[ht][0], s));
            mx[ht][1] = fmaxf(mx[ht][1], __shfl_xor_sync(0xffffffffu, mx[ht][1], s));
        }
    }
    if (lane < 4) {
#pragma unroll
        for (int ht = 0; ht < 8; ht++) {
            int h = ht * 8 + 2 * lane;
            float v0 = fmaxf(mx[ht][0] + b2[h], 0.f);
            float v1 = fmaxf(mx[ht][1] + b2[h + 1], 0.f);
            // relu output >= 0: int-ordered atomicMax exact; out pre-zeroed in prep
            atomicMax((int*)&out[i * HDIM + h],     __float_as_int(v0));
            atomicMax((int*)&out[i * HDIM + h + 1], __float_as_int(v1));
        }
    }
}

// ---------------------------------------------------------------------------
extern "C" void kernel_launch(void* const* d_in, const int* in_sizes, int n_in,
                              void* d_out, int out_size) {
    const float* hidden = (const float*)d_in[0];
    const float* gt     = (const float*)d_in[1];
    const float* We     = (const float*)d_in[2];
    const float* be     = (const float*)d_in[3];
    const float* W1     = (const float*)d_in[4];
    const float* b1     = (const float*)d_in[5];
    const float* W2     = (const float*)d_in[6];
    const float* b2     = (const float*)d_in[7];
    float* out = (float*)d_out;

    prep_kernel<<<NPTS, MDIM>>>(hidden, gt, We, be, W1, b1, W2, out);
    main_kernel<<<(NPTS / IPB) * JSPLIT, THREADS>>>(b2, out);
}